// round 10
// baseline (speedup 1.0000x reference)
#include <cuda_runtime.h>
#include <math.h>
#include <cstdint>

#define B_   128
#define T_   512
#define D_   256
#define H_   512
#define G4_  2048   // 4*H

// ---- static device scratch ----
__device__ float g_xp[(size_t)T_ * B_ * G4_];   // [T*B, 4H] x-projections (+biases)
__device__ float g_h[2][B_ * H_];               // ping-pong h, paired-fragment layout per row
__device__ unsigned g_count = 0;                // grid barrier counter
__device__ volatile unsigned g_gen = 0;         // grid barrier generation

// =====================================================================
// helpers
// =====================================================================
__device__ __forceinline__ float tf32r(float x) {
    float y; asm("cvt.rna.tf32.f32 %0, %1;" : "=f"(y) : "f"(x)); return y;
}
__device__ __forceinline__ void mma1688(float* c, const uint32_t* a, const uint32_t* b) {
    asm volatile(
        "mma.sync.aligned.m16n8k8.row.col.f32.tf32.tf32.f32 "
        "{%0,%1,%2,%3}, {%4,%5,%6,%7}, {%8,%9}, {%0,%1,%2,%3};"
        : "+f"(c[0]), "+f"(c[1]), "+f"(c[2]), "+f"(c[3])
        : "r"(a[0]), "r"(a[1]), "r"(a[2]), "r"(a[3]), "r"(b[0]), "r"(b[1]));
}
__device__ __forceinline__ float fcomp(const float4& v, int i) {
    return i == 0 ? v.x : (i == 1 ? v.y : (i == 2 ? v.z : v.w));
}
__device__ __forceinline__ void grid_barrier(int step, unsigned ncta)
{
    __syncthreads();
    if (threadIdx.x == 0) {
        unsigned next = (unsigned)((step + 1) & (T_ - 1));
        __threadfence();
        unsigned old = atomicAdd(&g_count, 1u);
        if (old == ncta - 1u) {
            g_count = 0;
            __threadfence();
            g_gen = next;
        } else {
            while (g_gen != next) { }
        }
        __threadfence();
    }
    __syncthreads();
}

// =====================================================================
// Kernel 1: x_proj GEMM via tf32 mma (round-3 proven version, unchanged)
// =====================================================================
#define XA_STR 68
#define XB_STR 68
#define XP_SMEM ((128 * XA_STR + 64 * XB_STR) * 4)

__global__ void __launch_bounds__(256, 1) xproj_mma(
    const float* __restrict__ x,     // [B*T, D]
    const float* __restrict__ Wih,   // [4H, D]
    const float* __restrict__ bih,
    const float* __restrict__ bhh)
{
    extern __shared__ float sm[];
    float* Ash = sm;                   // [128][68]
    float* Bsh = sm + 128 * XA_STR;    // [64][68]

    const int tid  = threadIdx.x;
    const int wid  = tid >> 5;
    const int lane = tid & 31;
    const int g    = lane >> 2;
    const int tig  = lane & 3;
    const int wm   = wid & 3;
    const int wcol = (wid >> 2) * 32;

    const int mt = blockIdx.x >> 5;
    const int nt = blockIdx.x & 31;
    const int m0 = mt * 128;
    const int n0 = nt * 64;

    float c[2][4][4];
#pragma unroll
    for (int a = 0; a < 2; ++a)
#pragma unroll
        for (int b = 0; b < 4; ++b)
#pragma unroll
            for (int i = 0; i < 4; ++i) c[a][b][i] = 0.f;

    for (int kc = 0; kc < 4; ++kc) {
        const int k0 = kc * 64;
        __syncthreads();
        {
            int row = tid >> 1;
            int h   = (tid & 1) * 32;
            const float* src = x + (size_t)(m0 + row) * D_ + k0 + h;
            float* dst = Ash + row * XA_STR + h;
#pragma unroll
            for (int i = 0; i < 8; ++i) {
                float4 v = *(const float4*)(src + i * 4);
                v.x = tf32r(v.x); v.y = tf32r(v.y); v.z = tf32r(v.z); v.w = tf32r(v.w);
                *(float4*)(dst + i * 4) = v;
            }
        }
        {
            int n = tid >> 2;
            int h = (tid & 3) * 16;
            const float* src = Wih + (size_t)(n0 + n) * D_ + k0 + h;
            float* dst = Bsh + n * XB_STR + h;
#pragma unroll
            for (int i = 0; i < 4; ++i) {
                float4 v = *(const float4*)(src + i * 4);
                v.x = tf32r(v.x); v.y = tf32r(v.y); v.z = tf32r(v.z); v.w = tf32r(v.w);
                *(float4*)(dst + i * 4) = v;
            }
        }
        __syncthreads();

        const float* a0p = Ash + (wm * 32 + g) * XA_STR;
        const float* a1p = a0p + 8 * XA_STR;
        const float* a2p = a0p + 16 * XA_STR;
        const float* a3p = a0p + 24 * XA_STR;
        const float* bp0 = Bsh + (wcol + 0  + g) * XB_STR;
        const float* bp1 = Bsh + (wcol + 8  + g) * XB_STR;
        const float* bp2 = Bsh + (wcol + 16 + g) * XB_STR;
        const float* bp3 = Bsh + (wcol + 24 + g) * XB_STR;

#pragma unroll 4
        for (int kk = 0; kk < 8; ++kk) {
            const int k8 = kk * 8 + tig;
            uint32_t af0[4] = { __float_as_uint(a0p[k8]), __float_as_uint(a1p[k8]),
                                __float_as_uint(a0p[k8 + 4]), __float_as_uint(a1p[k8 + 4]) };
            uint32_t af1[4] = { __float_as_uint(a2p[k8]), __float_as_uint(a3p[k8]),
                                __float_as_uint(a2p[k8 + 4]), __float_as_uint(a3p[k8 + 4]) };
            uint32_t bf0[2] = { __float_as_uint(bp0[k8]), __float_as_uint(bp0[k8 + 4]) };
            uint32_t bf1[2] = { __float_as_uint(bp1[k8]), __float_as_uint(bp1[k8 + 4]) };
            uint32_t bf2[2] = { __float_as_uint(bp2[k8]), __float_as_uint(bp2[k8 + 4]) };
            uint32_t bf3[2] = { __float_as_uint(bp3[k8]), __float_as_uint(bp3[k8 + 4]) };
            mma1688(c[0][0], af0, bf0); mma1688(c[0][1], af0, bf1);
            mma1688(c[0][2], af0, bf2); mma1688(c[0][3], af0, bf3);
            mma1688(c[1][0], af1, bf0); mma1688(c[1][1], af1, bf1);
            mma1688(c[1][2], af1, bf2); mma1688(c[1][3], af1, bf3);
        }
    }

    float2 bias[4];
#pragma unroll
    for (int nf = 0; nf < 4; ++nf) {
        int col = n0 + wcol + nf * 8 + 2 * tig;
        bias[nf].x = bih[col] + bhh[col];
        bias[nf].y = bih[col + 1] + bhh[col + 1];
    }
#pragma unroll
    for (int mf = 0; mf < 2; ++mf) {
#pragma unroll
        for (int rs = 0; rs < 2; ++rs) {
            int grow = m0 + wm * 32 + mf * 16 + g + rs * 8;
            int b = grow >> 9;
            int t = grow & 511;
            float* orow = g_xp + ((size_t)t * B_ + b) * G4_ + n0 + wcol + 2 * tig;
#pragma unroll
            for (int nf = 0; nf < 4; ++nf) {
                float2 v;
                v.x = c[mf][nf][rs * 2 + 0] + bias[nf].x;
                v.y = c[mf][nf][rs * 2 + 1] + bias[nf].y;
                *(float2*)(orow + nf * 8) = v;
            }
        }
    }
}

// =====================================================================
// Kernel 2: persistent recurrence (round-3 skeleton, paired LDS.128 frags).
//   128 CTAs (4 bt x 32 jt) x 256 threads.
//   Warps 0-3 compute gate q = wid; warp tile M=32, N=16, K=512.
//   Wsh/Hsh: stride 528 floats (2112 B == 64 mod 128 -> conflict-free LDS.128).
//   Paired 16-block: float4 at [blk*16 + tq*4] holds k = blk*16 + {tq,tq+4,tq+8,tq+12}.
//   g_h rows stored in the same paired order -> contiguous staging.
// =====================================================================
#define WSTR 528
#define HSH_OFF (64 * WSTR)
#define GSH_OFF (96 * WSTR)
#define REC_SMEM ((96 * WSTR + 32 * 68) * 4)    // 211456 B

__global__ void __launch_bounds__(256, 1) lstm_rec_mma(
    const float* __restrict__ Whh,   // [4H, H]
    float* __restrict__ out)         // [T*B, H]
{
    extern __shared__ float sm[];
    float* Wsh = sm;                  // [64 n][528] paired
    float* Hsh = sm + HSH_OFF;        // [32 b][528] paired
    float* Gsh = sm + GSH_OFF;        // [32 b][68]

    const int tid  = threadIdx.x;
    const int wid  = tid >> 5;
    const int lane = tid & 31;
    const int g    = lane >> 2;       // 0..7
    const int tq   = lane & 3;        // 0..3
    const int bt = blockIdx.x >> 5;
    const int jt = blockIdx.x & 31;
    const int b0 = bt * 32;
    const int j0 = jt * 16;

    // ---- one-time: pack W_hh slice [64 n][512 k] into paired SMEM (row n = gate*16+jl) ----
    {
        int n    = tid >> 2;
        int kseg = (tid & 3) * 128;
        int gate = n >> 4, jl = n & 15;
        const float* src = Whh + (size_t)(gate * H_ + j0 + jl) * H_ + kseg;
        float* dst = Wsh + n * WSTR;
#pragma unroll 8
        for (int k = 0; k < 128; k += 4) {
            float4 v = *(const float4*)(src + k);
            int ka  = kseg + k;
            int base = (ka >> 4) * 16;
            int e   = ((ka >> 2) & 1) + 2 * ((ka >> 3) & 1);
            dst[base + 0  + e] = tf32r(v.x);
            dst[base + 4  + e] = tf32r(v.y);
            dst[base + 8  + e] = tf32r(v.z);
            dst[base + 12 + e] = tf32r(v.w);
        }
    }
    __syncthreads();

    const int q = wid;                // compute warps 0-3: gate index

    // cell ownership: 2 elements per thread (round-3 mapping)
    const int eb = tid >> 3;          // 0..31
    const int ej = (tid * 2) & 15;    // even local j
    float c_reg[2] = {0.f, 0.f};

    // staging mapping (all 8 warps): warp wid rows wid*4+rr;
    // lane covers blocks (lane>>2)+8*ii, chunk lane&3 -> conflict-free, coalesced.
    const int srow0 = wid * 4;
    const int sblk  = lane >> 2;
    const int sc    = lane & 3;

    // xp prefetch regs (compute warps): acc-init for current t
    float pf[2][2][4];
    if (wid < 4) {
        const float* xb = g_xp + (size_t)b0 * G4_ + q * 512 + j0 + 2 * tq;
#pragma unroll
        for (int m = 0; m < 2; ++m)
#pragma unroll
            for (int rs = 0; rs < 2; ++rs) {
                const float* r = xb + (size_t)(m * 16 + g + rs * 8) * G4_;
#pragma unroll
                for (int f = 0; f < 2; ++f) {
                    float2 v = *(const float2*)(r + f * 8);
                    pf[m][f][rs * 2 + 0] = v.x;
                    pf[m][f][rs * 2 + 1] = v.y;
                }
            }
    }

    for (int t = 0; t < T_; ++t) {
        // ---- stage h_{t-1} (all 8 warps, __ldcg float4, paired-contiguous) ----
        if (t > 0) {
            const float* hb = g_h[(t - 1) & 1];
#pragma unroll
            for (int rr = 0; rr < 4; ++rr) {
                int row = srow0 + rr;
                const float* src = hb + (size_t)(b0 + row) * 512;
                float* dst = Hsh + row * WSTR;
#pragma unroll
                for (int ii = 0; ii < 4; ++ii) {
                    int off = (sblk + 8 * ii) * 16 + sc * 4;
                    float4 v = __ldcg((const float4*)(src + off));
                    *(float4*)(dst + off) = v;
                }
            }
        }
        __syncthreads();

        // ---- compute warps: acc init from xp, mma over K=512 (paired LDS.128) ----
        if (wid < 4) {
            float acc[2][2][4];
#pragma unroll
            for (int m = 0; m < 2; ++m)
#pragma unroll
                for (int f = 0; f < 2; ++f)
#pragma unroll
                    for (int i = 0; i < 4; ++i) acc[m][f][i] = pf[m][f][i];

            if (t > 0) {
                const float* Ha = Hsh + g * WSTR + tq * 4;
                const float* Wb = Wsh + (q * 16 + g) * WSTR + tq * 4;
#pragma unroll 4
                for (int z = 0; z < 32; ++z) {
                    const int offz = z * 16;
                    float4 a4[4];
#pragma unroll
                    for (int r = 0; r < 4; ++r)
                        a4[r] = *(const float4*)(Ha + r * 8 * WSTR + offz);
                    float4 b4[2];
#pragma unroll
                    for (int f = 0; f < 2; ++f)
                        b4[f] = *(const float4*)(Wb + f * 8 * WSTR + offz);
#pragma unroll
                    for (int s2 = 0; s2 < 2; ++s2) {
#pragma unroll
                        for (int m = 0; m < 2; ++m) {
                            uint32_t aa[4] = {
                                __float_as_uint(fcomp(a4[2 * m],     2 * s2)),
                                __float_as_uint(fcomp(a4[2 * m + 1], 2 * s2)),
                                __float_as_uint(fcomp(a4[2 * m],     2 * s2 + 1)),
                                __float_as_uint(fcomp(a4[2 * m + 1], 2 * s2 + 1)) };
#pragma unroll
                            for (int f = 0; f < 2; ++f) {
                                uint32_t bb[2] = {
                                    __float_as_uint(fcomp(b4[f], 2 * s2)),
                                    __float_as_uint(fcomp(b4[f], 2 * s2 + 1)) };
                                mma1688(acc[m][f], aa, bb);
                            }
                        }
                    }
                }
            }
            // store gates to Gsh
#pragma unroll
            for (int m = 0; m < 2; ++m)
#pragma unroll
                for (int rs = 0; rs < 2; ++rs) {
                    float* gr = Gsh + (m * 16 + g + rs * 8) * 68 + q * 16 + 2 * tq;
#pragma unroll
                    for (int f = 0; f < 2; ++f) {
                        float2 v;
                        v.x = acc[m][f][rs * 2 + 0];
                        v.y = acc[m][f][rs * 2 + 1];
                        *(float2*)(gr + f * 8) = v;
                    }
                }
        }
        __syncthreads();

        // ---- prefetch xp for t+1 (compute warps; overlaps cell) ----
        if (wid < 4 && t + 1 < T_) {
            const float* xb = g_xp + ((size_t)(t + 1) * B_ + b0) * G4_ + q * 512 + j0 + 2 * tq;
#pragma unroll
            for (int m = 0; m < 2; ++m)
#pragma unroll
                for (int rs = 0; rs < 2; ++rs) {
                    const float* r = xb + (size_t)(m * 16 + g + rs * 8) * G4_;
#pragma unroll
                    for (int f = 0; f < 2; ++f) {
                        float2 v = *(const float2*)(r + f * 8);
                        pf[m][f][rs * 2 + 0] = v.x;
                        pf[m][f][rs * 2 + 1] = v.y;
                    }
                }
        }

        // ---- cell: 2 elements per thread ----
        {
            const float* gr = Gsh + eb * 68;
            float* hrow = g_h[t & 1] + (size_t)(b0 + eb) * 512;
            float* orow = out + ((size_t)t * B_ + b0 + eb) * H_ + j0;
#pragma unroll
            for (int p = 0; p < 2; ++p) {
                int jl = ej + p;
                float gi = gr[0  + jl];
                float gf = gr[16 + jl];
                float gg = gr[32 + jl];
                float go = gr[48 + jl];
                float i_s = 1.f / (1.f + __expf(-gi));
                float f_s = 1.f / (1.f + __expf(-gf));
                float o_s = 1.f / (1.f + __expf(-go));
                float g_t = tanhf(gg);
                float cv  = f_s * c_reg[p] + i_s * g_t;
                c_reg[p]  = cv;
                float hv  = o_s * tanhf(cv);
                orow[jl] = hv;
                int pos = jt * 16 + (jl & 3) * 4 + ((jl >> 2) & 1) + 2 * ((jl >> 3) & 1);
                hrow[pos] = tf32r(hv);
            }
        }

        grid_barrier(t, 128u);
    }
}

// =====================================================================
extern "C" void kernel_launch(void* const* d_in, const int* in_sizes, int n_in,
                              void* d_out, int out_size)
{
    const float* x   = (const float*)d_in[0];   // [B,T,D]
    const float* Wih = (const float*)d_in[1];   // [4H,D]
    const float* Whh = (const float*)d_in[2];   // [4H,H]
    const float* bih = (const float*)d_in[3];   // [4H]
    const float* bhh = (const float*)d_in[4];   // [4H]
    float* out = (float*)d_out;

    cudaFuncSetAttribute(xproj_mma,
                         cudaFuncAttributeMaxDynamicSharedMemorySize, XP_SMEM);
    xproj_mma<<<16384, 256, XP_SMEM>>>(x, Wih, bih, bhh);

    cudaFuncSetAttribute(lstm_rec_mma,
                         cudaFuncAttributeMaxDynamicSharedMemorySize, REC_SMEM);
    lstm_rec_mma<<<128, 256, REC_SMEM>>>(Whh, out);
}

// round 11
// speedup vs baseline: 1.4758x; 1.4758x over previous
#include <cuda_runtime.h>
#include <math.h>
#include <cstdint>

#define B_   128
#define T_   512
#define D_   256
#define H_   512
#define G4_  2048   // 4*H

// ---- static device scratch (no cudaMalloc allowed) ----
__device__ float g_xp[(size_t)T_ * B_ * G4_];   // [T*B, 4H] x-projections (+biases)
__device__ float g_h[2][B_ * H_];               // ping-pong hidden state (tf32-rounded)
__device__ unsigned g_cntB[128];                // 4 bt-group barrier counters, 128B apart
__device__ volatile unsigned g_genB[128];       // 4 bt-group barrier generations, 128B apart

// =====================================================================
// helpers
// =====================================================================
__device__ __forceinline__ float tf32r(float x) {
    float y; asm("cvt.rna.tf32.f32 %0, %1;" : "=f"(y) : "f"(x)); return y;
}

// mma.sync m16n8k8 tf32, fp32 accum (generic PTX, runs on HMMA pipe)
__device__ __forceinline__ void mma1688(float* c, const uint32_t* a, const uint32_t* b) {
    asm volatile(
        "mma.sync.aligned.m16n8k8.row.col.f32.tf32.tf32.f32 "
        "{%0,%1,%2,%3}, {%4,%5,%6,%7}, {%8,%9}, {%0,%1,%2,%3};"
        : "+f"(c[0]), "+f"(c[1]), "+f"(c[2]), "+f"(c[3])
        : "r"(a[0]), "r"(a[1]), "r"(a[2]), "r"(a[3]), "r"(b[0]), "r"(b[1]));
}

// 32-CTA bt-group barrier (independent per batch-tile group)
__device__ __forceinline__ void grid_barrier_bt(int step, int bt)
{
    __syncthreads();
    if (threadIdx.x == 0) {
        unsigned next = (unsigned)((step + 1) & (T_ - 1));
        __threadfence();
        unsigned old = atomicAdd(&g_cntB[bt * 32], 1u);
        if (old == 31u) {
            g_cntB[bt * 32] = 0;
            __threadfence();
            g_genB[bt * 32] = next;
        } else {
            while (g_genB[bt * 32] != next) { }
        }
        __threadfence();
    }
    __syncthreads();
}

// =====================================================================
// Kernel 1: x_proj GEMM via tf32 mma (round-3 proven version, unchanged)
//   grid = 512 m-tiles x 32 n-tiles; CTA tile M=128, N=64, K=256 (4 chunks of 64)
//   8 warps, each warp tile M=32 x N=32 (2 A-frags x 4 B-frags)
// =====================================================================
#define XA_STR 68      // A smem row stride (floats), pad 4
#define XB_STR 68
#define XP_SMEM ((128 * XA_STR + 64 * XB_STR) * 4)

__global__ void __launch_bounds__(256, 1) xproj_mma(
    const float* __restrict__ x,     // [B*T, D]
    const float* __restrict__ Wih,   // [4H, D]
    const float* __restrict__ bih,
    const float* __restrict__ bhh)
{
    extern __shared__ float sm[];
    float* Ash = sm;                   // [128][68]
    float* Bsh = sm + 128 * XA_STR;    // [64][68]

    const int tid  = threadIdx.x;
    const int wid  = tid >> 5;
    const int lane = tid & 31;
    const int g    = lane >> 2;        // 0..7
    const int tig  = lane & 3;         // 0..3
    const int wm   = wid & 3;          // M warp 0..3 (rows wm*32)
    const int wcol = (wid >> 2) * 32;  // N warp col base: 0 or 32

    const int mt = blockIdx.x >> 5;
    const int nt = blockIdx.x & 31;
    const int m0 = mt * 128;
    const int n0 = nt * 64;

    float c[2][4][4];
#pragma unroll
    for (int a = 0; a < 2; ++a)
#pragma unroll
        for (int b = 0; b < 4; ++b)
#pragma unroll
            for (int i = 0; i < 4; ++i) c[a][b][i] = 0.f;

    for (int kc = 0; kc < 4; ++kc) {
        const int k0 = kc * 64;
        __syncthreads();
        // stage A chunk: 128 rows x 64 k (tf32-rounded)
        {
            int row = tid >> 1;
            int h   = (tid & 1) * 32;
            const float* src = x + (size_t)(m0 + row) * D_ + k0 + h;
            float* dst = Ash + row * XA_STR + h;
#pragma unroll
            for (int i = 0; i < 8; ++i) {
                float4 v = *(const float4*)(src + i * 4);
                v.x = tf32r(v.x); v.y = tf32r(v.y); v.z = tf32r(v.z); v.w = tf32r(v.w);
                *(float4*)(dst + i * 4) = v;
            }
        }
        // stage B chunk: 64 n x 64 k
        {
            int n = tid >> 2;
            int h = (tid & 3) * 16;
            const float* src = Wih + (size_t)(n0 + n) * D_ + k0 + h;
            float* dst = Bsh + n * XB_STR + h;
#pragma unroll
            for (int i = 0; i < 4; ++i) {
                float4 v = *(const float4*)(src + i * 4);
                v.x = tf32r(v.x); v.y = tf32r(v.y); v.z = tf32r(v.z); v.w = tf32r(v.w);
                *(float4*)(dst + i * 4) = v;
            }
        }
        __syncthreads();

        const float* a0p = Ash + (wm * 32 + g) * XA_STR;
        const float* a1p = a0p + 8 * XA_STR;
        const float* a2p = a0p + 16 * XA_STR;
        const float* a3p = a0p + 24 * XA_STR;
        const float* bp0 = Bsh + (wcol + 0  + g) * XB_STR;
        const float* bp1 = Bsh + (wcol + 8  + g) * XB_STR;
        const float* bp2 = Bsh + (wcol + 16 + g) * XB_STR;
        const float* bp3 = Bsh + (wcol + 24 + g) * XB_STR;

#pragma unroll 4
        for (int kk = 0; kk < 8; ++kk) {
            const int k8 = kk * 8 + tig;
            uint32_t af0[4] = { __float_as_uint(a0p[k8]), __float_as_uint(a1p[k8]),
                                __float_as_uint(a0p[k8 + 4]), __float_as_uint(a1p[k8 + 4]) };
            uint32_t af1[4] = { __float_as_uint(a2p[k8]), __float_as_uint(a3p[k8]),
                                __float_as_uint(a2p[k8 + 4]), __float_as_uint(a3p[k8 + 4]) };
            uint32_t bf0[2] = { __float_as_uint(bp0[k8]), __float_as_uint(bp0[k8 + 4]) };
            uint32_t bf1[2] = { __float_as_uint(bp1[k8]), __float_as_uint(bp1[k8 + 4]) };
            uint32_t bf2[2] = { __float_as_uint(bp2[k8]), __float_as_uint(bp2[k8 + 4]) };
            uint32_t bf3[2] = { __float_as_uint(bp3[k8]), __float_as_uint(bp3[k8 + 4]) };
            mma1688(c[0][0], af0, bf0); mma1688(c[0][1], af0, bf1);
            mma1688(c[0][2], af0, bf2); mma1688(c[0][3], af0, bf3);
            mma1688(c[1][0], af1, bf0); mma1688(c[1][1], af1, bf1);
            mma1688(c[1][2], af1, bf2); mma1688(c[1][3], af1, bf3);
        }
    }

    // epilogue: bias add + remap row (b*T+t -> t*B+b), float2 stores
    float2 bias[4];
#pragma unroll
    for (int nf = 0; nf < 4; ++nf) {
        int col = n0 + wcol + nf * 8 + 2 * tig;
        bias[nf].x = bih[col] + bhh[col];
        bias[nf].y = bih[col + 1] + bhh[col + 1];
    }
#pragma unroll
    for (int mf = 0; mf < 2; ++mf) {
#pragma unroll
        for (int rs = 0; rs < 2; ++rs) {
            int grow = m0 + wm * 32 + mf * 16 + g + rs * 8;
            int b = grow >> 9;         // / T_
            int t = grow & 511;
            float* orow = g_xp + ((size_t)t * B_ + b) * G4_ + n0 + wcol + 2 * tig;
#pragma unroll
            for (int nf = 0; nf < 4; ++nf) {
                float2 v;
                v.x = c[mf][nf][rs * 2 + 0] + bias[nf].x;
                v.y = c[mf][nf][rs * 2 + 1] + bias[nf].y;
                *(float2*)(orow + nf * 8) = v;
            }
        }
    }
}

// =====================================================================
// Kernel 2: persistent tf32 mma recurrence (round-3 exact, split barrier).
//   128 CTAs = 4 b-tiles x 32 j-tiles; CTA tile M=32(batch), N=64(4 gates x 16), K=512
//   256 threads; warps 0-3 compute (warp tile M=32 x N=16); all warps stage/cell
// =====================================================================
#define W_STR 516           // Wsh/Hsh row stride (floats), pad 4
#define G_STR 68
#define REC_SMEM ((64 * W_STR + 32 * W_STR + 32 * G_STR) * 4)

__global__ void __launch_bounds__(256, 1) lstm_rec_mma(
    const float* __restrict__ Whh,   // [4H, H]
    float* __restrict__ out)         // [T*B, H]
{
    extern __shared__ float sm[];
    float* Wsh = sm;                     // [64 n][516]
    float* Hsh = sm + 64 * W_STR;        // [32 b][516]
    float* Gsh = Hsh + 32 * W_STR;       // [32 b][68]

    const int tid  = threadIdx.x;
    const int wid  = tid >> 5;
    const int lane = tid & 31;
    const int g    = lane >> 2;
    const int tig  = lane & 3;

    const int bt = blockIdx.x >> 5;
    const int jt = blockIdx.x & 31;
    const int b0 = bt * 32;
    const int j0 = jt * 16;

    // ---- one-time: W_hh slice [64 n][512 k] -> SMEM (tf32-rna) ----
    {
        int n  = tid >> 2;               // 0..63 : n = q*16 + jl
        int kq = (tid & 3) * 128;
        int q  = n >> 4, jl = n & 15;
        const float* wr = Whh + (size_t)(q * H_ + j0 + jl) * H_ + kq;
        float* dst = Wsh + n * W_STR + kq;
#pragma unroll 8
        for (int i = 0; i < 128; i += 4) {
            float4 v = *(const float4*)(wr + i);
            v.x = tf32r(v.x); v.y = tf32r(v.y); v.z = tf32r(v.z); v.w = tf32r(v.w);
            *(float4*)(dst + i) = v;
        }
    }
    __syncthreads();

    // compute-warp constants (warps 0-3); warp w owns gate q=w, cols wn0..wn0+15
    const int wn0 = wid * 16;

    // cell state: thread owns (b = tid>>3, j = (tid&7)*2 .. +1)
    const int cb = tid >> 3;
    const int cj = (tid & 7) * 2;
    float c_reg[2] = {0.f, 0.f};

    // accumulators + xp prefetch (warps 0-3 only meaningful)
    float c[2][2][4];
    float pf[2][2][4];

    // prefetch xp for t=0
    if (wid < 4) {
        const float* xb = g_xp + ((size_t)0 * B_ + b0) * G4_ + wid * 512 + j0 + 2 * tig;
#pragma unroll
        for (int mf = 0; mf < 2; ++mf)
#pragma unroll
            for (int rs = 0; rs < 2; ++rs) {
                const float* r = xb + (size_t)(mf * 16 + g + rs * 8) * G4_;
#pragma unroll
                for (int nf = 0; nf < 2; ++nf) {
                    float2 v = *(const float2*)(r + nf * 8);
                    pf[mf][nf][rs * 2 + 0] = v.x;
                    pf[mf][nf][rs * 2 + 1] = v.y;
                }
            }
    }

    for (int t = 0; t < T_; ++t) {
        if (wid < 4) {
#pragma unroll
            for (int mf = 0; mf < 2; ++mf)
#pragma unroll
                for (int nf = 0; nf < 2; ++nf)
#pragma unroll
                    for (int i = 0; i < 4; ++i) c[mf][nf][i] = pf[mf][nf][i];
        }

        if (t > 0) {
            // stage h_{t-1}: [32 b][512], L2-coherent loads
            {
                int row = tid >> 3;
                int s   = (tid & 7) * 4;
                const float* src = g_h[(t - 1) & 1] + (size_t)(b0 + row) * H_ + s;
                float* dst = Hsh + row * W_STR + s;
#pragma unroll
                for (int i = 0; i < 16; ++i) {
                    float4 v = __ldcg((const float4*)(src + i * 32));
                    *(float4*)(dst + i * 32) = v;
                }
            }
            __syncthreads();

            if (wid < 4) {
                const float* h0p = Hsh + g * W_STR;
                const float* h1p = Hsh + (g + 8) * W_STR;
                const float* h2p = Hsh + (16 + g) * W_STR;
                const float* h3p = Hsh + (24 + g) * W_STR;
                const float* w0p = Wsh + (wn0 + g) * W_STR;
                const float* w1p = Wsh + (wn0 + 8 + g) * W_STR;
#pragma unroll 4
                for (int kk = 0; kk < 64; ++kk) {
                    const int k8 = kk * 8 + tig;
                    uint32_t af0[4] = { __float_as_uint(h0p[k8]), __float_as_uint(h1p[k8]),
                                        __float_as_uint(h0p[k8 + 4]), __float_as_uint(h1p[k8 + 4]) };
                    uint32_t af1[4] = { __float_as_uint(h2p[k8]), __float_as_uint(h3p[k8]),
                                        __float_as_uint(h2p[k8 + 4]), __float_as_uint(h3p[k8 + 4]) };
                    uint32_t bf0[2] = { __float_as_uint(w0p[k8]), __float_as_uint(w0p[k8 + 4]) };
                    uint32_t bf1[2] = { __float_as_uint(w1p[k8]), __float_as_uint(w1p[k8 + 4]) };
                    mma1688(c[0][0], af0, bf0); mma1688(c[0][1], af0, bf1);
                    mma1688(c[1][0], af1, bf0); mma1688(c[1][1], af1, bf1);
                }
            }
        }

        // stage gates to SMEM
        if (wid < 4) {
#pragma unroll
            for (int mf = 0; mf < 2; ++mf)
#pragma unroll
                for (int rs = 0; rs < 2; ++rs) {
                    float* gr = Gsh + (mf * 16 + g + rs * 8) * G_STR + wn0 + 2 * tig;
#pragma unroll
                    for (int nf = 0; nf < 2; ++nf) {
                        float2 v;
                        v.x = c[mf][nf][rs * 2 + 0];
                        v.y = c[mf][nf][rs * 2 + 1];
                        *(float2*)(gr + nf * 8) = v;
                    }
                }
        }
        __syncthreads();

        // prefetch xp for t+1 (independent of this step's cell)
        if (wid < 4 && t + 1 < T_) {
            const float* xb = g_xp + ((size_t)(t + 1) * B_ + b0) * G4_ + wid * 512 + j0 + 2 * tig;
#pragma unroll
            for (int mf = 0; mf < 2; ++mf)
#pragma unroll
                for (int rs = 0; rs < 2; ++rs) {
                    const float* r = xb + (size_t)(mf * 16 + g + rs * 8) * G4_;
#pragma unroll
                    for (int nf = 0; nf < 2; ++nf) {
                        float2 v = *(const float2*)(r + nf * 8);
                        pf[mf][nf][rs * 2 + 0] = v.x;
                        pf[mf][nf][rs * 2 + 1] = v.y;
                    }
                }
        }

        // fused LSTM cell: 2 elements per thread, c in registers
        {
            const float* gr = Gsh + cb * G_STR;
            float h2[2];
#pragma unroll
            for (int p = 0; p < 2; ++p) {
                int j = cj + p;
                float gi = gr[0  + j];
                float gf = gr[16 + j];
                float gg = gr[32 + j];
                float go = gr[48 + j];
                float i_s = 1.f / (1.f + __expf(-gi));
                float f_s = 1.f / (1.f + __expf(-gf));
                float o_s = 1.f / (1.f + __expf(-go));
                float g_t = tanhf(gg);
                float cv  = f_s * c_reg[p] + i_s * g_t;
                c_reg[p]  = cv;
                h2[p]     = o_s * tanhf(cv);
            }
            float* op = out + ((size_t)t * B_ + b0 + cb) * H_ + j0 + cj;
            float2 ov; ov.x = h2[0]; ov.y = h2[1];
            *(float2*)op = ov;
            float* hp = g_h[t & 1] + (size_t)(b0 + cb) * H_ + j0 + cj;
            float2 hv; hv.x = tf32r(h2[0]); hv.y = tf32r(h2[1]);
            *(float2*)hp = hv;
        }

        grid_barrier_bt(t, bt);   // 32-CTA bt-group barrier (only dependency set)
    }
}

// =====================================================================
extern "C" void kernel_launch(void* const* d_in, const int* in_sizes, int n_in,
                              void* d_out, int out_size)
{
    const float* x   = (const float*)d_in[0];   // [B,T,D]
    const float* Wih = (const float*)d_in[1];   // [4H,D]
    const float* Whh = (const float*)d_in[2];   // [4H,H]
    const float* bih = (const float*)d_in[3];   // [4H]
    const float* bhh = (const float*)d_in[4];   // [4H]
    float* out = (float*)d_out;

    cudaFuncSetAttribute(xproj_mma,
                         cudaFuncAttributeMaxDynamicSharedMemorySize, XP_SMEM);
    xproj_mma<<<16384, 256, XP_SMEM>>>(x, Wih, bih, bhh);

    cudaFuncSetAttribute(lstm_rec_mma,
                         cudaFuncAttributeMaxDynamicSharedMemorySize, REC_SMEM);
    lstm_rec_mma<<<128, 256, REC_SMEM>>>(Whh, out);
}

// round 12
// speedup vs baseline: 1.5594x; 1.0567x over previous
#include <cuda_runtime.h>
#include <math.h>
#include <cstdint>

#define B_   128
#define T_   512
#define D_   256
#define H_   512
#define G4_  2048   // 4*H

// ---- static device scratch (no cudaMalloc allowed) ----
__device__ float g_xp[(size_t)T_ * B_ * G4_];   // [T*B, 4H] x-projections (+biases)
__device__ float g_h[2][B_ * H_];               // ping-pong hidden state (tf32-rounded)
__device__ unsigned g_cntB[128];                // 4 bt-group barrier counters, 128B apart
__device__ volatile unsigned g_genB[128];       // 4 bt-group barrier generations

// =====================================================================
// helpers
// =====================================================================
__device__ __forceinline__ float tf32r(float x) {
    float y; asm("cvt.rna.tf32.f32 %0, %1;" : "=f"(y) : "f"(x)); return y;
}
__device__ __forceinline__ uint32_t smem_u32(const void* p) {
    uint32_t a;
    asm("{ .reg .u64 t; cvta.to.shared.u64 t, %1; cvt.u32.u64 %0, t; }" : "=r"(a) : "l"(p));
    return a;
}
// ldmatrix x4: four 8x8 b16 tiles == one 16x8 tf32 A-frag or two 8x8 tf32 B-frags
__device__ __forceinline__ void ldsm4(uint32_t* r, uint32_t addr) {
    asm volatile("ldmatrix.sync.aligned.m8n8.x4.shared.b16 {%0,%1,%2,%3}, [%4];"
                 : "=r"(r[0]), "=r"(r[1]), "=r"(r[2]), "=r"(r[3]) : "r"(addr));
}
// mma.sync m16n8k8 tf32, fp32 accum
__device__ __forceinline__ void mma1688(float* c, const uint32_t* a, const uint32_t* b) {
    asm volatile(
        "mma.sync.aligned.m16n8k8.row.col.f32.tf32.tf32.f32 "
        "{%0,%1,%2,%3}, {%4,%5,%6,%7}, {%8,%9}, {%0,%1,%2,%3};"
        : "+f"(c[0]), "+f"(c[1]), "+f"(c[2]), "+f"(c[3])
        : "r"(a[0]), "r"(a[1]), "r"(a[2]), "r"(a[3]), "r"(b[0]), "r"(b[1]));
}
// 32-CTA bt-group barrier
__device__ __forceinline__ void grid_barrier_bt(int step, int bt)
{
    __syncthreads();
    if (threadIdx.x == 0) {
        unsigned next = (unsigned)((step + 1) & (T_ - 1));
        __threadfence();
        unsigned old = atomicAdd(&g_cntB[bt * 32], 1u);
        if (old == 31u) {
            g_cntB[bt * 32] = 0;
            __threadfence();
            g_genB[bt * 32] = next;
        } else {
            while (g_genB[bt * 32] != next) { }
        }
        __threadfence();
    }
    __syncthreads();
}

// =====================================================================
// Kernel 1: x_proj GEMM via tf32 mma (round-3 proven version, unchanged)
// =====================================================================
#define XA_STR 68
#define XB_STR 68
#define XP_SMEM ((128 * XA_STR + 64 * XB_STR) * 4)

__global__ void __launch_bounds__(256, 1) xproj_mma(
    const float* __restrict__ x,     // [B*T, D]
    const float* __restrict__ Wih,   // [4H, D]
    const float* __restrict__ bih,
    const float* __restrict__ bhh)
{
    extern __shared__ float sm[];
    float* Ash = sm;                   // [128][68]
    float* Bsh = sm + 128 * XA_STR;    // [64][68]

    const int tid  = threadIdx.x;
    const int wid  = tid >> 5;
    const int lane = tid & 31;
    const int g    = lane >> 2;
    const int tig  = lane & 3;
    const int wm   = wid & 3;
    const int wcol = (wid >> 2) * 32;

    const int mt = blockIdx.x >> 5;
    const int nt = blockIdx.x & 31;
    const int m0 = mt * 128;
    const int n0 = nt * 64;

    float c[2][4][4];
#pragma unroll
    for (int a = 0; a < 2; ++a)
#pragma unroll
        for (int b = 0; b < 4; ++b)
#pragma unroll
            for (int i = 0; i < 4; ++i) c[a][b][i] = 0.f;

    for (int kc = 0; kc < 4; ++kc) {
        const int k0 = kc * 64;
        __syncthreads();
        {
            int row = tid >> 1;
            int h   = (tid & 1) * 32;
            const float* src = x + (size_t)(m0 + row) * D_ + k0 + h;
            float* dst = Ash + row * XA_STR + h;
#pragma unroll
            for (int i = 0; i < 8; ++i) {
                float4 v = *(const float4*)(src + i * 4);
                v.x = tf32r(v.x); v.y = tf32r(v.y); v.z = tf32r(v.z); v.w = tf32r(v.w);
                *(float4*)(dst + i * 4) = v;
            }
        }
        {
            int n = tid >> 2;
            int h = (tid & 3) * 16;
            const float* src = Wih + (size_t)(n0 + n) * D_ + k0 + h;
            float* dst = Bsh + n * XB_STR + h;
#pragma unroll
            for (int i = 0; i < 4; ++i) {
                float4 v = *(const float4*)(src + i * 4);
                v.x = tf32r(v.x); v.y = tf32r(v.y); v.z = tf32r(v.z); v.w = tf32r(v.w);
                *(float4*)(dst + i * 4) = v;
            }
        }
        __syncthreads();

        const float* a0p = Ash + (wm * 32 + g) * XA_STR;
        const float* a1p = a0p + 8 * XA_STR;
        const float* a2p = a0p + 16 * XA_STR;
        const float* a3p = a0p + 24 * XA_STR;
        const float* bp0 = Bsh + (wcol + 0  + g) * XB_STR;
        const float* bp1 = Bsh + (wcol + 8  + g) * XB_STR;
        const float* bp2 = Bsh + (wcol + 16 + g) * XB_STR;
        const float* bp3 = Bsh + (wcol + 24 + g) * XB_STR;

#pragma unroll 4
        for (int kk = 0; kk < 8; ++kk) {
            const int k8 = kk * 8 + tig;
            uint32_t af0[4] = { __float_as_uint(a0p[k8]), __float_as_uint(a1p[k8]),
                                __float_as_uint(a0p[k8 + 4]), __float_as_uint(a1p[k8 + 4]) };
            uint32_t af1[4] = { __float_as_uint(a2p[k8]), __float_as_uint(a3p[k8]),
                                __float_as_uint(a2p[k8 + 4]), __float_as_uint(a3p[k8 + 4]) };
            uint32_t bf0[2] = { __float_as_uint(bp0[k8]), __float_as_uint(bp0[k8 + 4]) };
            uint32_t bf1[2] = { __float_as_uint(bp1[k8]), __float_as_uint(bp1[k8 + 4]) };
            uint32_t bf2[2] = { __float_as_uint(bp2[k8]), __float_as_uint(bp2[k8 + 4]) };
            uint32_t bf3[2] = { __float_as_uint(bp3[k8]), __float_as_uint(bp3[k8 + 4]) };
            mma1688(c[0][0], af0, bf0); mma1688(c[0][1], af0, bf1);
            mma1688(c[0][2], af0, bf2); mma1688(c[0][3], af0, bf3);
            mma1688(c[1][0], af1, bf0); mma1688(c[1][1], af1, bf1);
            mma1688(c[1][2], af1, bf2); mma1688(c[1][3], af1, bf3);
        }
    }

    float2 bias[4];
#pragma unroll
    for (int nf = 0; nf < 4; ++nf) {
        int col = n0 + wcol + nf * 8 + 2 * tig;
        bias[nf].x = bih[col] + bhh[col];
        bias[nf].y = bih[col + 1] + bhh[col + 1];
    }
#pragma unroll
    for (int mf = 0; mf < 2; ++mf) {
#pragma unroll
        for (int rs = 0; rs < 2; ++rs) {
            int grow = m0 + wm * 32 + mf * 16 + g + rs * 8;
            int b = grow >> 9;
            int t = grow & 511;
            float* orow = g_xp + ((size_t)t * B_ + b) * G4_ + n0 + wcol + 2 * tig;
#pragma unroll
            for (int nf = 0; nf < 4; ++nf) {
                float2 v;
                v.x = c[mf][nf][rs * 2 + 0] + bias[nf].x;
                v.y = c[mf][nf][rs * 2 + 1] + bias[nf].y;
                *(float2*)(orow + nf * 8) = v;
            }
        }
    }
}

// =====================================================================
// Kernel 2: persistent tf32 mma recurrence (round-3/11 skeleton,
//           operand loads via ldmatrix.x4 — SAME operand placement,
//           bit-identical numerics, 1024 -> 448 instrs per warp/step).
//   128 CTAs = 4 bt x 32 jt; CTA tile M=32, N=64 (4 gates x 16), K=512.
//   256 threads; warps 0-3 compute (warp tile M=32 x N=16).
//   W_STR=516 floats: row stride 2064 B == 16 mod 128 -> ldmatrix
//   tile rows hit 8 distinct 16B banks (conflict-free).
// =====================================================================
#define W_STR 516           // Wsh/Hsh row stride (floats), pad 4
#define G_STR 68
#define REC_SMEM ((64 * W_STR + 32 * W_STR + 32 * G_STR) * 4)

__global__ void __launch_bounds__(256, 1) lstm_rec_mma(
    const float* __restrict__ Whh,   // [4H, H]
    float* __restrict__ out)         // [T*B, H]
{
    extern __shared__ float sm[];
    float* Wsh = sm;                     // [64 n][516]
    float* Hsh = sm + 64 * W_STR;        // [32 b][516]
    float* Gsh = Hsh + 32 * W_STR;       // [32 b][68]
    const uint32_t sb = smem_u32(sm);

    const int tid  = threadIdx.x;
    const int wid  = tid >> 5;
    const int lane = tid & 31;
    const int g    = lane >> 2;
    const int tig  = lane & 3;

    const int bt = blockIdx.x >> 5;
    const int jt = blockIdx.x & 31;
    const int b0 = bt * 32;
    const int j0 = jt * 16;

    // ---- one-time: W_hh slice [64 n][512 k] -> SMEM (tf32-rna) ----
    {
        int n  = tid >> 2;               // 0..63 : n = q*16 + jl
        int kq = (tid & 3) * 128;
        int q  = n >> 4, jl = n & 15;
        const float* wr = Whh + (size_t)(q * H_ + j0 + jl) * H_ + kq;
        float* dst = Wsh + n * W_STR + kq;
#pragma unroll 8
        for (int i = 0; i < 128; i += 4) {
            float4 v = *(const float4*)(wr + i);
            v.x = tf32r(v.x); v.y = tf32r(v.y); v.z = tf32r(v.z); v.w = tf32r(v.w);
            *(float4*)(dst + i) = v;
        }
    }
    __syncthreads();

    // compute-warp constants (warps 0-3); warp w owns gate q=w, cols wn0..wn0+15
    const int wn0 = wid * 16;

    // ldmatrix per-lane addresses (byte offsets into dynamic smem):
    // A (16x8 tf32 frag): lanes 0-15 -> rows (lane&15), k+0; lanes 16-31 -> rows (lane&15), k+4
    const uint32_t aAddr1 = sb + (uint32_t)((64 * W_STR) + (lane & 15) * W_STR + ((lane >> 4) << 2)) * 4;
    const uint32_t aAddr2 = aAddr1 + (uint32_t)(16 * W_STR) * 4;
    // B (two 8x8 tf32 frags): r0,r1 = rows wn0..+7 (k+0, k+4); r2,r3 = rows wn0+8..+15
    const uint32_t bAddr  = sb + (uint32_t)((wn0 + (lane & 7) + ((lane >> 4) << 3)) * W_STR
                                            + (((lane >> 3) & 1) << 2)) * 4;

    // cell state: thread owns (b = tid>>3, j = (tid&7)*2 .. +1)
    const int cb = tid >> 3;
    const int cj = (tid & 7) * 2;
    float c_reg[2] = {0.f, 0.f};

    float c[2][2][4];
    float pf[2][2][4];

    // prefetch xp for t=0
    if (wid < 4) {
        const float* xb = g_xp + ((size_t)0 * B_ + b0) * G4_ + wid * 512 + j0 + 2 * tig;
#pragma unroll
        for (int mf = 0; mf < 2; ++mf)
#pragma unroll
            for (int rs = 0; rs < 2; ++rs) {
                const float* r = xb + (size_t)(mf * 16 + g + rs * 8) * G4_;
#pragma unroll
                for (int nf = 0; nf < 2; ++nf) {
                    float2 v = *(const float2*)(r + nf * 8);
                    pf[mf][nf][rs * 2 + 0] = v.x;
                    pf[mf][nf][rs * 2 + 1] = v.y;
                }
            }
    }

    for (int t = 0; t < T_; ++t) {
        if (wid < 4) {
#pragma unroll
            for (int mf = 0; mf < 2; ++mf)
#pragma unroll
                for (int nf = 0; nf < 2; ++nf)
#pragma unroll
                    for (int i = 0; i < 4; ++i) c[mf][nf][i] = pf[mf][nf][i];
        }

        if (t > 0) {
            // stage h_{t-1}: [32 b][512], L2-coherent loads
            {
                int row = tid >> 3;
                int s   = (tid & 7) * 4;
                const float* src = g_h[(t - 1) & 1] + (size_t)(b0 + row) * H_ + s;
                float* dst = Hsh + row * W_STR + s;
#pragma unroll
                for (int i = 0; i < 16; ++i) {
                    float4 v = __ldcg((const float4*)(src + i * 32));
                    *(float4*)(dst + i * 32) = v;
                }
            }
            __syncthreads();

            if (wid < 4) {
#pragma unroll 4
                for (int kk = 0; kk < 64; ++kk) {
                    const uint32_t koff = (uint32_t)kk * 32;   // 8 floats per k-step
                    uint32_t af0[4], af1[4], bb[4];
                    ldsm4(af0, aAddr1 + koff);
                    ldsm4(af1, aAddr2 + koff);
                    ldsm4(bb,  bAddr  + koff);
                    mma1688(c[0][0], af0, bb);     mma1688(c[0][1], af0, bb + 2);
                    mma1688(c[1][0], af1, bb);     mma1688(c[1][1], af1, bb + 2);
                }
            }
        }

        // stage gates to SMEM
        if (wid < 4) {
#pragma unroll
            for (int mf = 0; mf < 2; ++mf)
#pragma unroll
                for (int rs = 0; rs < 2; ++rs) {
                    float* gr = Gsh + (mf * 16 + g + rs * 8) * G_STR + wn0 + 2 * tig;
#pragma unroll
                    for (int nf = 0; nf < 2; ++nf) {
                        float2 v;
                        v.x = c[mf][nf][rs * 2 + 0];
                        v.y = c[mf][nf][rs * 2 + 1];
                        *(float2*)(gr + nf * 8) = v;
                    }
                }
        }
        __syncthreads();

        // prefetch xp for t+1 (independent of this step's cell)
        if (wid < 4 && t + 1 < T_) {
            const float* xb = g_xp + ((size_t)(t + 1) * B_ + b0) * G4_ + wid * 512 + j0 + 2 * tig;
#pragma unroll
            for (int mf = 0; mf < 2; ++mf)
#pragma unroll
                for (int rs = 0; rs < 2; ++rs) {
                    const float* r = xb + (size_t)(mf * 16 + g + rs * 8) * G4_;
#pragma unroll
                    for (int nf = 0; nf < 2; ++nf) {
                        float2 v = *(const float2*)(r + nf * 8);
                        pf[mf][nf][rs * 2 + 0] = v.x;
                        pf[mf][nf][rs * 2 + 1] = v.y;
                    }
                }
        }

        // fused LSTM cell: 2 elements per thread, c in registers
        {
            const float* gr = Gsh + cb * G_STR;
            float h2[2];
#pragma unroll
            for (int p = 0; p < 2; ++p) {
                int j = cj + p;
                float gi = gr[0  + j];
                float gf = gr[16 + j];
                float gg = gr[32 + j];
                float go = gr[48 + j];
                float i_s = 1.f / (1.f + __expf(-gi));
                float f_s = 1.f / (1.f + __expf(-gf));
                float o_s = 1.f / (1.f + __expf(-go));
                float g_t = tanhf(gg);
                float cv  = f_s * c_reg[p] + i_s * g_t;
                c_reg[p]  = cv;
                h2[p]     = o_s * tanhf(cv);
            }
            float* op = out + ((size_t)t * B_ + b0 + cb) * H_ + j0 + cj;
            float2 ov; ov.x = h2[0]; ov.y = h2[1];
            *(float2*)op = ov;
            float* hp = g_h[t & 1] + (size_t)(b0 + cb) * H_ + j0 + cj;
            float2 hv; hv.x = tf32r(h2[0]); hv.y = tf32r(h2[1]);
            *(float2*)hp = hv;
        }

        grid_barrier_bt(t, bt);
    }
}

// =====================================================================
extern "C" void kernel_launch(void* const* d_in, const int* in_sizes, int n_in,
                              void* d_out, int out_size)
{
    const float* x   = (const float*)d_in[0];   // [B,T,D]
    const float* Wih = (const float*)d_in[1];   // [4H,D]
    const float* Whh = (const float*)d_in[2];   // [4H,H]
    const float* bih = (const float*)d_in[3];   // [4H]
    const float* bhh = (const float*)d_in[4];   // [4H]
    float* out = (float*)d_out;

    cudaFuncSetAttribute(xproj_mma,
                         cudaFuncAttributeMaxDynamicSharedMemorySize, XP_SMEM);
    xproj_mma<<<16384, 256, XP_SMEM>>>(x, Wih, bih, bhh);

    cudaFuncSetAttribute(lstm_rec_mma,
                         cudaFuncAttributeMaxDynamicSharedMemorySize, REC_SMEM);
    lstm_rec_mma<<<128, 256, REC_SMEM>>>(Whh, out);
}

// round 13
// speedup vs baseline: 1.5668x; 1.0047x over previous
#include <cuda_runtime.h>
#include <math.h>
#include <cstdint>

#define B_   128
#define T_   512
#define D_   256
#define H_   512
#define G4_  2048   // 4*H

// ---- static device scratch (no cudaMalloc allowed) ----
__device__ float g_xp[(size_t)T_ * B_ * G4_];   // [T*B, 4H] x-projections (+biases)
__device__ float g_h[2][B_ * H_];               // ping-pong hidden state (tf32-rounded)
__device__ unsigned g_cntB[128];                // 4 bt-group barrier counters, 128B apart
__device__ volatile unsigned g_genB[128];       // 4 bt-group barrier generations

// =====================================================================
// helpers
// =====================================================================
__device__ __forceinline__ float tf32r(float x) {
    float y; asm("cvt.rna.tf32.f32 %0, %1;" : "=f"(y) : "f"(x)); return y;
}
__device__ __forceinline__ uint32_t smem_u32(const void* p) {
    uint32_t a;
    asm("{ .reg .u64 t; cvta.to.shared.u64 t, %1; cvt.u32.u64 %0, t; }" : "=r"(a) : "l"(p));
    return a;
}
// ldmatrix x4: four 8x8 b16 tiles == one 16x8 tf32 A-frag or two 8x8 tf32 B-frags
__device__ __forceinline__ void ldsm4(uint32_t* r, uint32_t addr) {
    asm volatile("ldmatrix.sync.aligned.m8n8.x4.shared.b16 {%0,%1,%2,%3}, [%4];"
                 : "=r"(r[0]), "=r"(r[1]), "=r"(r[2]), "=r"(r[3]) : "r"(addr));
}
// mma.sync m16n8k8 tf32, fp32 accum
__device__ __forceinline__ void mma1688(float* c, const uint32_t* a, const uint32_t* b) {
    asm volatile(
        "mma.sync.aligned.m16n8k8.row.col.f32.tf32.tf32.f32 "
        "{%0,%1,%2,%3}, {%4,%5,%6,%7}, {%8,%9}, {%0,%1,%2,%3};"
        : "+f"(c[0]), "+f"(c[1]), "+f"(c[2]), "+f"(c[3])
        : "r"(a[0]), "r"(a[1]), "r"(a[2]), "r"(a[3]), "r"(b[0]), "r"(b[1]));
}
// 32-CTA bt-group barrier
__device__ __forceinline__ void grid_barrier_bt(int step, int bt)
{
    __syncthreads();
    if (threadIdx.x == 0) {
        unsigned next = (unsigned)((step + 1) & (T_ - 1));
        __threadfence();
        unsigned old = atomicAdd(&g_cntB[bt * 32], 1u);
        if (old == 31u) {
            g_cntB[bt * 32] = 0;
            __threadfence();
            g_genB[bt * 32] = next;
        } else {
            while (g_genB[bt * 32] != next) { }
        }
        __threadfence();
    }
    __syncthreads();
}

// =====================================================================
// Kernel 1: x_proj GEMM via tf32 mma + ldmatrix operand loads.
//   grid = 512 m-tiles x 32 n-tiles; CTA tile M=128, N=64, K=256 (4 chunks)
//   8 warps, warp tile 32x32. Same operand placement as the manual loads
//   (pattern bit-identically verified in the recurrence kernel).
//   XA_STR=68 floats: row stride 272 B == 16 mod 128 -> ldmatrix tile rows
//   hit banks r*17 mod 8 = r mod 8 (all distinct) -> conflict-free.
// =====================================================================
#define XA_STR 68
#define XB_STR 68
#define XP_SMEM ((128 * XA_STR + 64 * XB_STR) * 4)

__global__ void __launch_bounds__(256, 1) xproj_mma(
    const float* __restrict__ x,     // [B*T, D]
    const float* __restrict__ Wih,   // [4H, D]
    const float* __restrict__ bih,
    const float* __restrict__ bhh)
{
    extern __shared__ float sm[];
    float* Ash = sm;                   // [128][68]
    float* Bsh = sm + 128 * XA_STR;    // [64][68]
    const uint32_t sb = smem_u32(sm);

    const int tid  = threadIdx.x;
    const int wid  = tid >> 5;
    const int lane = tid & 31;
    const int g    = lane >> 2;
    const int tig  = lane & 3;
    const int wm   = wid & 3;
    const int wcol = (wid >> 2) * 32;

    const int mt = blockIdx.x >> 5;
    const int nt = blockIdx.x & 31;
    const int m0 = mt * 128;
    const int n0 = nt * 64;

    // ldmatrix per-lane addresses (byte offsets into dynamic smem)
    // A tiles: lanes 0-15 -> rows wm*32+(lane&15) @k; lanes 16-31 -> same rows @k+4
    const uint32_t aAddr1 = sb + (uint32_t)((wm * 32 + (lane & 15)) * XA_STR + ((lane >> 4) << 2)) * 4;
    const uint32_t aAddr2 = aAddr1 + (uint32_t)(16 * XA_STR) * 4;
    // B tiles: rows wcol+(lane&7)+((lane>>4)<<3), col offset ((lane>>3)&1)*4 floats
    const uint32_t bBase  = sb + (uint32_t)(128 * XA_STR) * 4;
    const uint32_t bAddr1 = bBase + (uint32_t)((wcol + (lane & 7) + ((lane >> 4) << 3)) * XB_STR
                                               + (((lane >> 3) & 1) << 2)) * 4;
    const uint32_t bAddr2 = bAddr1 + (uint32_t)(16 * XB_STR) * 4;

    float c[2][4][4];
#pragma unroll
    for (int a = 0; a < 2; ++a)
#pragma unroll
        for (int b = 0; b < 4; ++b)
#pragma unroll
            for (int i = 0; i < 4; ++i) c[a][b][i] = 0.f;

    for (int kc = 0; kc < 4; ++kc) {
        const int k0 = kc * 64;
        __syncthreads();
        // stage A chunk: 128 rows x 64 k (tf32-rounded)
        {
            int row = tid >> 1;
            int h   = (tid & 1) * 32;
            const float* src = x + (size_t)(m0 + row) * D_ + k0 + h;
            float* dst = Ash + row * XA_STR + h;
#pragma unroll
            for (int i = 0; i < 8; ++i) {
                float4 v = *(const float4*)(src + i * 4);
                v.x = tf32r(v.x); v.y = tf32r(v.y); v.z = tf32r(v.z); v.w = tf32r(v.w);
                *(float4*)(dst + i * 4) = v;
            }
        }
        // stage B chunk: 64 n x 64 k
        {
            int n = tid >> 2;
            int h = (tid & 3) * 16;
            const float* src = Wih + (size_t)(n0 + n) * D_ + k0 + h;
            float* dst = Bsh + n * XB_STR + h;
#pragma unroll
            for (int i = 0; i < 4; ++i) {
                float4 v = *(const float4*)(src + i * 4);
                v.x = tf32r(v.x); v.y = tf32r(v.y); v.z = tf32r(v.z); v.w = tf32r(v.w);
                *(float4*)(dst + i * 4) = v;
            }
        }
        __syncthreads();

#pragma unroll 4
        for (int kk = 0; kk < 8; ++kk) {
            const uint32_t koff = (uint32_t)kk * 32;   // 8 floats per k-step
            uint32_t af0[4], af1[4], bb01[4], bb23[4];
            ldsm4(af0,  aAddr1 + koff);
            ldsm4(af1,  aAddr2 + koff);
            ldsm4(bb01, bAddr1 + koff);
            ldsm4(bb23, bAddr2 + koff);
            mma1688(c[0][0], af0, bb01); mma1688(c[0][1], af0, bb01 + 2);
            mma1688(c[0][2], af0, bb23); mma1688(c[0][3], af0, bb23 + 2);
            mma1688(c[1][0], af1, bb01); mma1688(c[1][1], af1, bb01 + 2);
            mma1688(c[1][2], af1, bb23); mma1688(c[1][3], af1, bb23 + 2);
        }
    }

    // epilogue: bias add + remap row (b*T+t -> t*B+b), float2 stores
    float2 bias[4];
#pragma unroll
    for (int nf = 0; nf < 4; ++nf) {
        int col = n0 + wcol + nf * 8 + 2 * tig;
        bias[nf].x = bih[col] + bhh[col];
        bias[nf].y = bih[col + 1] + bhh[col + 1];
    }
#pragma unroll
    for (int mf = 0; mf < 2; ++mf) {
#pragma unroll
        for (int rs = 0; rs < 2; ++rs) {
            int grow = m0 + wm * 32 + mf * 16 + g + rs * 8;
            int b = grow >> 9;
            int t = grow & 511;
            float* orow = g_xp + ((size_t)t * B_ + b) * G4_ + n0 + wcol + 2 * tig;
#pragma unroll
            for (int nf = 0; nf < 4; ++nf) {
                float2 v;
                v.x = c[mf][nf][rs * 2 + 0] + bias[nf].x;
                v.y = c[mf][nf][rs * 2 + 1] + bias[nf].y;
                *(float2*)(orow + nf * 8) = v;
            }
        }
    }
}

// =====================================================================
// Kernel 2: persistent tf32 mma recurrence (round-12 exact — current best)
// =====================================================================
#define W_STR 516           // Wsh/Hsh row stride (floats), pad 4
#define G_STR 68
#define REC_SMEM ((64 * W_STR + 32 * W_STR + 32 * G_STR) * 4)

__global__ void __launch_bounds__(256, 1) lstm_rec_mma(
    const float* __restrict__ Whh,   // [4H, H]
    float* __restrict__ out)         // [T*B, H]
{
    extern __shared__ float sm[];
    float* Wsh = sm;                     // [64 n][516]
    float* Hsh = sm + 64 * W_STR;        // [32 b][516]
    float* Gsh = Hsh + 32 * W_STR;       // [32 b][68]
    const uint32_t sb = smem_u32(sm);

    const int tid  = threadIdx.x;
    const int wid  = tid >> 5;
    const int lane = tid & 31;
    const int g    = lane >> 2;
    const int tig  = lane & 3;

    const int bt = blockIdx.x >> 5;
    const int jt = blockIdx.x & 31;
    const int b0 = bt * 32;
    const int j0 = jt * 16;

    // ---- one-time: W_hh slice [64 n][512 k] -> SMEM (tf32-rna) ----
    {
        int n  = tid >> 2;               // 0..63 : n = q*16 + jl
        int kq = (tid & 3) * 128;
        int q  = n >> 4, jl = n & 15;
        const float* wr = Whh + (size_t)(q * H_ + j0 + jl) * H_ + kq;
        float* dst = Wsh + n * W_STR + kq;
#pragma unroll 8
        for (int i = 0; i < 128; i += 4) {
            float4 v = *(const float4*)(wr + i);
            v.x = tf32r(v.x); v.y = tf32r(v.y); v.z = tf32r(v.z); v.w = tf32r(v.w);
            *(float4*)(dst + i) = v;
        }
    }
    __syncthreads();

    // compute-warp constants (warps 0-3); warp w owns gate q=w, cols wn0..wn0+15
    const int wn0 = wid * 16;

    // ldmatrix per-lane addresses (byte offsets into dynamic smem):
    const uint32_t aAddr1 = sb + (uint32_t)((64 * W_STR) + (lane & 15) * W_STR + ((lane >> 4) << 2)) * 4;
    const uint32_t aAddr2 = aAddr1 + (uint32_t)(16 * W_STR) * 4;
    const uint32_t bAddr  = sb + (uint32_t)((wn0 + (lane & 7) + ((lane >> 4) << 3)) * W_STR
                                            + (((lane >> 3) & 1) << 2)) * 4;

    // cell state: thread owns (b = tid>>3, j = (tid&7)*2 .. +1)
    const int cb = tid >> 3;
    const int cj = (tid & 7) * 2;
    float c_reg[2] = {0.f, 0.f};

    float c[2][2][4];
    float pf[2][2][4];

    // prefetch xp for t=0
    if (wid < 4) {
        const float* xb = g_xp + ((size_t)0 * B_ + b0) * G4_ + wid * 512 + j0 + 2 * tig;
#pragma unroll
        for (int mf = 0; mf < 2; ++mf)
#pragma unroll
            for (int rs = 0; rs < 2; ++rs) {
                const float* r = xb + (size_t)(mf * 16 + g + rs * 8) * G4_;
#pragma unroll
                for (int nf = 0; nf < 2; ++nf) {
                    float2 v = *(const float2*)(r + nf * 8);
                    pf[mf][nf][rs * 2 + 0] = v.x;
                    pf[mf][nf][rs * 2 + 1] = v.y;
                }
            }
    }

    for (int t = 0; t < T_; ++t) {
        if (wid < 4) {
#pragma unroll
            for (int mf = 0; mf < 2; ++mf)
#pragma unroll
                for (int nf = 0; nf < 2; ++nf)
#pragma unroll
                    for (int i = 0; i < 4; ++i) c[mf][nf][i] = pf[mf][nf][i];
        }

        if (t > 0) {
            // stage h_{t-1}: [32 b][512], L2-coherent loads
            {
                int row = tid >> 3;
                int s   = (tid & 7) * 4;
                const float* src = g_h[(t - 1) & 1] + (size_t)(b0 + row) * H_ + s;
                float* dst = Hsh + row * W_STR + s;
#pragma unroll
                for (int i = 0; i < 16; ++i) {
                    float4 v = __ldcg((const float4*)(src + i * 32));
                    *(float4*)(dst + i * 32) = v;
                }
            }
            __syncthreads();

            if (wid < 4) {
#pragma unroll 4
                for (int kk = 0; kk < 64; ++kk) {
                    const uint32_t koff = (uint32_t)kk * 32;   // 8 floats per k-step
                    uint32_t af0[4], af1[4], bb[4];
                    ldsm4(af0, aAddr1 + koff);
                    ldsm4(af1, aAddr2 + koff);
                    ldsm4(bb,  bAddr  + koff);
                    mma1688(c[0][0], af0, bb);     mma1688(c[0][1], af0, bb + 2);
                    mma1688(c[1][0], af1, bb);     mma1688(c[1][1], af1, bb + 2);
                }
            }
        }

        // stage gates to SMEM
        if (wid < 4) {
#pragma unroll
            for (int mf = 0; mf < 2; ++mf)
#pragma unroll
                for (int rs = 0; rs < 2; ++rs) {
                    float* gr = Gsh + (mf * 16 + g + rs * 8) * G_STR + wn0 + 2 * tig;
#pragma unroll
                    for (int nf = 0; nf < 2; ++nf) {
                        float2 v;
                        v.x = c[mf][nf][rs * 2 + 0];
                        v.y = c[mf][nf][rs * 2 + 1];
                        *(float2*)(gr + nf * 8) = v;
                    }
                }
        }
        __syncthreads();

        // prefetch xp for t+1 (independent of this step's cell)
        if (wid < 4 && t + 1 < T_) {
            const float* xb = g_xp + ((size_t)(t + 1) * B_ + b0) * G4_ + wid * 512 + j0 + 2 * tig;
#pragma unroll
            for (int mf = 0; mf < 2; ++mf)
#pragma unroll
                for (int rs = 0; rs < 2; ++rs) {
                    const float* r = xb + (size_t)(mf * 16 + g + rs * 8) * G4_;
#pragma unroll
                    for (int nf = 0; nf < 2; ++nf) {
                        float2 v = *(const float2*)(r + nf * 8);
                        pf[mf][nf][rs * 2 + 0] = v.x;
                        pf[mf][nf][rs * 2 + 1] = v.y;
                    }
                }
        }

        // fused LSTM cell: 2 elements per thread, c in registers
        {
            const float* gr = Gsh + cb * G_STR;
            float h2[2];
#pragma unroll
            for (int p = 0; p < 2; ++p) {
                int j = cj + p;
                float gi = gr[0  + j];
                float gf = gr[16 + j];
                float gg = gr[32 + j];
                float go = gr[48 + j];
                float i_s = 1.f / (1.f + __expf(-gi));
                float f_s = 1.f / (1.f + __expf(-gf));
                float o_s = 1.f / (1.f + __expf(-go));
                float g_t = tanhf(gg);
                float cv  = f_s * c_reg[p] + i_s * g_t;
                c_reg[p]  = cv;
                h2[p]     = o_s * tanhf(cv);
            }
            float* op = out + ((size_t)t * B_ + b0 + cb) * H_ + j0 + cj;
            float2 ov; ov.x = h2[0]; ov.y = h2[1];
            *(float2*)op = ov;
            float* hp = g_h[t & 1] + (size_t)(b0 + cb) * H_ + j0 + cj;
            float2 hv; hv.x = tf32r(h2[0]); hv.y = tf32r(h2[1]);
            *(float2*)hp = hv;
        }

        grid_barrier_bt(t, bt);
    }
}

// =====================================================================
extern "C" void kernel_launch(void* const* d_in, const int* in_sizes, int n_in,
                              void* d_out, int out_size)
{
    const float* x   = (const float*)d_in[0];   // [B,T,D]
    const float* Wih = (const float*)d_in[1];   // [4H,D]
    const float* Whh = (const float*)d_in[2];   // [4H,H]
    const float* bih = (const float*)d_in[3];   // [4H]
    const float* bhh = (const float*)d_in[4];   // [4H]
    float* out = (float*)d_out;

    cudaFuncSetAttribute(xproj_mma,
                         cudaFuncAttributeMaxDynamicSharedMemorySize, XP_SMEM);
    xproj_mma<<<16384, 256, XP_SMEM>>>(x, Wih, bih, bhh);

    cudaFuncSetAttribute(lstm_rec_mma,
                         cudaFuncAttributeMaxDynamicSharedMemorySize, REC_SMEM);
    lstm_rec_mma<<<128, 256, REC_SMEM>>>(Whh, out);
}